// round 15
// baseline (speedup 1.0000x reference)
#include <cuda_runtime.h>
#include <cuda_fp16.h>
#include <math.h>

// Problem constants (fixed by reference)
#define B_     32
#define L_     16000
#define CF_    5
#define LN2F   0.69314718055994531f
#define HLN2F  0.34657359027997264f   // 0.5*ln2

// Tiling: 56 loci per CTA -> 286 CTAs (<= 296 co-residency slots = 148 SMs x 2,
// forced by __launch_bounds__(1024,2)). Even tiles => exact symmetric split.
#define LC     56
#define NB     286
#define NR2    125                     // r2 blocks after barrier: 125*1024 = 128000
#define SROW   33                      // smem row stride (elements)

#define SCALE_JS   4294967296.0f       // 2^32
#define ISCALE_JS  (1.0 / 4294967296.0)
#define SCALE_S    1048576.0f          // 2^20 (ce, r2)
#define ISCALE_S   (1.0 / 1048576.0)

// ---- scratch (device globals, zero-initialized at module load) ----
__device__ float          g_pred[L_ * 8];          // [locus][group]
__device__ unsigned char  g_altp[L_ * 8];          // alt_cnt | (nonmiss<<4)
__device__ int            g_nm_tot[8];             // per-group nonmiss totals
__device__ long long      g_js_acc[1024];          // fixed-point per pair
__device__ int            g_cnt_acc[1024];
__device__ long long      g_ce_acc, g_r2_acc;
__device__ unsigned int   g_done, g_done2;

// ============================================================================
// Single persistent kernel: phase 1 = staging + CE + r2 partials + symmetric
// pairwise JS with direct fixed-point accumulation; grid barrier (load-poll);
// phase 2 = r2 reduction (125 blocks); last-done r2 block finalizes + resets.
// ============================================================================
__global__ void __launch_bounds__(1024, 2) k_fused(
    const float4* __restrict__ logits4,   // (B, L) float4 (C=4)
    const float4* __restrict__ prob4,
    const float*  __restrict__ ytrue,     // (B, L, 5)
    const float*  __restrict__ yevo,      // (B, B)
    float*        __restrict__ out)
{
    __shared__ uint2    s_p[LC * SROW];   // 4 x fp16 clamped prob
    __shared__ unsigned s_m[LC * SROW];   // (bf16 h' << 16) | label
    __shared__ int      s_nm[8];
    __shared__ float    s_red[32];
    __shared__ float    s_j[1024];        // finalize staging
    __shared__ int      s_c[1024];
    __shared__ int      s_last;

    const int tid  = threadIdx.x;
    const int lane = tid & 31;
    const int w    = tid >> 5;
    const int bid  = blockIdx.x;
    const int l0   = bid * LC;
    const int nloc = min(LC, L_ - l0);     // 56 or 40 (even)
    const int n32  = nloc * 32;
    const int H    = nloc >> 1;

    if (tid < 8) s_nm[tid] = 0;
    __syncthreads();

    // ---- phase 1a: staging (coalesced; lanes walk consecutive loci) ----
    float ce_acc = 0.0f;
    for (int e = tid; e < n32; e += 1024) {
        int i  = e / nloc;                // batch
        int ll = e - i * nloc;            // local locus
        size_t gi = (size_t)i * L_ + l0 + ll;

        const float* yt = ytrue + gi * CF_;
        float lf = yt[1] + 2.0f * yt[2] + 3.0f * yt[3] + 4.0f * yt[4];
        int lbl = (int)(lf + 0.5f);

        float4 lg = logits4[gi];
        float m  = fmaxf(fmaxf(lg.x, lg.y), fmaxf(lg.z, lg.w));
        float se = __expf(lg.x - m) + __expf(lg.y - m) +
                   __expf(lg.z - m) + __expf(lg.w - m);
        if (lbl != 4) {
            float sel = (lbl == 0) ? lg.x : (lbl == 1) ? lg.y : (lbl == 2) ? lg.z : lg.w;
            ce_acc += (m + LN2F * __log2f(se)) - sel;
        }

        float4 p = prob4[gi];
        float a = fmaxf(p.x, 1e-7f), b = fmaxf(p.y, 1e-7f);
        float c = fmaxf(p.z, 1e-7f), d = fmaxf(p.w, 1e-7f);
        float hp = a * __log2f(a) + b * __log2f(b) +
                   c * __log2f(c) + d * __log2f(d) + (a + b + c + d);
        unsigned hb = (__float_as_uint(hp) + 0x8000u) & 0xFFFF0000u;

        __half2 p01 = __floats2half2_rn(a, b);
        __half2 p23 = __floats2half2_rn(c, d);
        int idx = ll * SROW + i;
        s_p[idx] = make_uint2(reinterpret_cast<unsigned&>(p01),
                              reinterpret_cast<unsigned&>(p23));
        s_m[idx] = hb | (unsigned)lbl;
    }

    // CE: warp partials -> CTA sum -> one deterministic fixed-point atomic
#pragma unroll
    for (int o = 16; o > 0; o >>= 1) ce_acc += __shfl_xor_sync(0xFFFFFFFFu, ce_acc, o);
    if (lane == 0) s_red[w] = ce_acc;
    __syncthreads();
    if (tid == 0) {
        float s = 0.0f;
#pragma unroll
        for (int k = 0; k < 32; ++k) s += s_red[k];
        atomicAdd((unsigned long long*)&g_ce_acc,
                  (unsigned long long)(long long)(s * SCALE_S));
    }

    // ---- phase 1b: r2 group partials ----
    if (tid < nloc * 8) {
        int g  = tid & 7;
        int ll = tid >> 3;
        int base = ll * SROW + g * 4;
        float pred = 0.0f;
        int alt = 0, nm = 0;
#pragma unroll
        for (int q = 0; q < 4; ++q) {
            uint2 u = s_p[base + q];
            float2 f01 = __half22float2(reinterpret_cast<__half2&>(u.x));
            float2 f23 = __half22float2(reinterpret_cast<__half2&>(u.y));
            pred += f01.y + f23.x + f23.y;
            int lb = s_m[base + q] & 0xFF;
            alt += (lb >= 1 && lb <= 3);
            nm  |= (lb != 4);
        }
        int l = l0 + ll;
        g_pred[l * 8 + g] = 0.25f * pred;
        g_altp[l * 8 + g] = (unsigned char)(alt | (nm << 4));
        if (nm) atomicAdd(&s_nm[g], 1);
    }
    __syncthreads();
    if (tid < 8) atomicAdd(&g_nm_tot[tid], s_nm[tid]);

    // ---- phase 1c: symmetric pairwise JS (proven uniform loop) ----
    const int i = w;
    const int j = lane;
    const int start = (j < i) ? H : 0;

    float js = 0.0f;
    int   cnt = 0;
#pragma unroll 2
    for (int k = 0; k < H; ++k) {
        const int row = (start + k) * SROW;
        unsigned wi = s_m[row + i];           // broadcast
        if ((wi & 0xFFu) == 4u) continue;     // warp-uniform skip (20% of loci)
        unsigned wj = s_m[row + j];
        bool act = (((wi ^ wj) & 0xFFu) == 0u);
        float msk = act ? 1.0f : 0.0f;
        uint2 ui = s_p[row + i];              // broadcast
        uint2 uj = s_p[row + j];
        __half2 s01 = __hadd2(reinterpret_cast<__half2&>(ui.x),
                              reinterpret_cast<__half2&>(uj.x));
        __half2 s23 = __hadd2(reinterpret_cast<__half2&>(ui.y),
                              reinterpret_cast<__half2&>(uj.y));
        float2 f01 = __half22float2(s01);
        float2 f23 = __half22float2(s23);
        float slog2 = f01.x * __log2f(f01.x) + f01.y * __log2f(f01.y) +
                      f23.x * __log2f(f23.x) + f23.y * __log2f(f23.y);
        float hsum = __uint_as_float(wi & 0xFFFF0000u) +
                     __uint_as_float(wj & 0xFFFF0000u);
        js  = fmaf(msk, hsum - slog2, js);    // HLN2F applied at finalize
        cnt += act;
    }

    // direct fixed-point accumulation (order-independent => deterministic)
    atomicAdd((unsigned long long*)&g_js_acc[tid],
              (unsigned long long)(long long)(js * SCALE_JS));
    if (cnt) atomicAdd(&g_cnt_acc[tid], cnt);

    // ---- grid-wide barrier: atomic arrival, NON-ATOMIC volatile load poll ----
    // (atomicOr polling serializes on the LTS atomic ALU: ~n_conc*32*0.854 cyc
    //  per round with 286 pollers; plain L2 reads don't.)
    __threadfence();
    __syncthreads();
    if (tid == 0) {
        atomicAdd(&g_done, 1u);
        while (*(volatile unsigned int*)&g_done < NB) __nanosleep(128);
    }
    __syncthreads();
    __threadfence();

    // blocks >= NR2 are done
    if (bid >= NR2) return;

    // ---- phase 2: r2 reduction; 125 blocks x 1024 = 128000 items exactly ----
    {
        if (tid < 8) s_nm[tid] = g_nm_tot[tid];
        __syncthreads();
        int idx = bid * 1024 + tid;
        int g = idx & 7;
        float cntg = fmaxf(4.0f * (float)s_nm[g], 1.0f);
        unsigned char pk = g_altp[idx];
        float alt = (float)(pk & 15);
        bool nonmiss = (pk & 16) != 0;
        float af2 = nonmiss ? (alt / cntg) : 0.5f;
        float r2acc = 0.0f;
        if (nonmiss && af2 != 0.0f && af2 != 1.0f) {
            float den = fmaxf(af2 * (1.0f - af2), 0.01f);
            float dd  = g_pred[idx] - af2;
            r2acc = dd * dd / den;
        }
#pragma unroll
        for (int o = 16; o > 0; o >>= 1) r2acc += __shfl_xor_sync(0xFFFFFFFFu, r2acc, o);
        if (lane == 0) s_red[w] = r2acc;
        __syncthreads();
        if (tid == 0) {
            float r2 = 0.0f;
#pragma unroll
            for (int k = 0; k < 32; ++k) r2 += s_red[k];
            atomicAdd((unsigned long long*)&g_r2_acc,
                      (unsigned long long)(long long)(r2 * SCALE_S));
        }
    }

    // ---- completion counter among r2 blocks; last finalizes ----
    __threadfence();
    __syncthreads();
    if (tid == 0) s_last = (atomicAdd(&g_done2, 1u) == NR2 - 1);
    __syncthreads();
    if (!s_last) return;
    __threadfence();

    // evo combine: transpose symmetric halves, weights, output
    s_j[tid] = (float)((double)g_js_acc[tid] * ISCALE_JS);
    s_c[tid] = g_cnt_acc[tid];
    __syncthreads();
    const int tT = lane * 32 + w;
    float jsv = HLN2F * (s_j[tid] + s_j[tT]) /
                fmaxf((float)(s_c[tid] + s_c[tT]), 1.0f);
    float wgt = __expf(-yevo[tid]);
    float rs = wgt;
#pragma unroll
    for (int o = 16; o > 0; o >>= 1) rs += __shfl_xor_sync(0xFFFFFFFFu, rs, o);
    float term = (wgt / (rs + 1e-8f)) * jsv;
#pragma unroll
    for (int o = 16; o > 0; o >>= 1) term += __shfl_xor_sync(0xFFFFFFFFu, term, o);
    __syncthreads();
    if (lane == 0) s_red[w] = term;
    __syncthreads();
    if (tid == 0) {
        float evo = 0.0f;
#pragma unroll
        for (int k = 0; k < 32; ++k) evo += s_red[k];
        float ce = (float)((double)g_ce_acc * ISCALE_S);
        float r2 = (float)((double)g_r2_acc * ISCALE_S);
        if (!isfinite(evo)) evo = 0.0f;
        out[0] = ce - 0.125f * r2 + evo;   // r2_loss = -sum*GS/B
    }

    // reset accumulators for the next graph replay
    __syncthreads();
    g_js_acc[tid] = 0ll;
    g_cnt_acc[tid] = 0;
    if (tid < 8) g_nm_tot[tid] = 0;
    if (tid == 0) { g_ce_acc = 0ll; g_r2_acc = 0ll; g_done = 0u; g_done2 = 0u; }
}

extern "C" void kernel_launch(void* const* d_in, const int* in_sizes, int n_in,
                              void* d_out, int out_size)
{
    const float* logits = (const float*)d_in[0];
    const float* prob   = (const float*)d_in[1];
    const float* ytrue  = (const float*)d_in[2];
    const float* yevo   = (const float*)d_in[3];

    k_fused<<<NB, 1024>>>((const float4*)logits, (const float4*)prob,
                          ytrue, yevo, (float*)d_out);
}

// round 16
// speedup vs baseline: 1.0802x; 1.0802x over previous
#include <cuda_runtime.h>
#include <cuda_fp16.h>
#include <math.h>

// Problem constants (fixed by reference)
#define B_     32
#define L_     16000
#define CF_    5
#define LN2F   0.69314718055994531f
#define HLN2F  0.34657359027997264f   // 0.5*ln2

// Tiling: 56 loci per CTA -> 286 CTAs (<= 296 co-residency slots = 148 SMs x 2,
// forced by __launch_bounds__(1024,2)). Even tiles => exact symmetric split.
#define LC     56
#define NB     286
#define SROW   33                      // smem row stride (elements)

#define SCALE_JS   4294967296.0f       // 2^32
#define ISCALE_JS  (1.0 / 4294967296.0)
#define SCALE_S    1048576.0f          // 2^20 (ce, bucket stats)
#define ISCALE_S   (1.0 / 1048576.0)

// ---- scratch (device globals, zero-initialized at module load) ----
__device__ int            g_nm_tot[8];             // per-group nonmiss locus totals
__device__ long long      g_S1[32], g_S2[32];      // r2 bucket stats (fixed-point)
__device__ int            g_N[32];                 // r2 bucket counts
__device__ long long      g_js_acc[1024];          // fixed-point per pair
__device__ int            g_cnt_acc[1024];
__device__ long long      g_ce_acc;
__device__ unsigned int   g_done;

// ============================================================================
// Single persistent kernel: staging + CE + r2 sufficient statistics +
// symmetric pairwise JS with direct fixed-point accumulation.
// NO grid barrier: the last-arriving CTA performs the closed-form finalize.
// ============================================================================
__global__ void __launch_bounds__(1024, 2) k_fused(
    const float4* __restrict__ logits4,   // (B, L) float4 (C=4)
    const float4* __restrict__ prob4,
    const float*  __restrict__ ytrue,     // (B, L, 5)
    const float*  __restrict__ yevo,      // (B, B)
    float*        __restrict__ out)
{
    __shared__ uint2    s_p[LC * SROW];   // 4 x fp16 clamped prob
    __shared__ unsigned s_m[LC * SROW];   // (bf16 h' << 16) | label
    __shared__ int      s_nm[8];
    __shared__ int      s_S1[32], s_S2[32], s_N[32];
    __shared__ float    s_red[32];
    __shared__ float    s_j[1024];        // finalize staging
    __shared__ int      s_c[1024];
    __shared__ int      s_last;

    const int tid  = threadIdx.x;
    const int lane = tid & 31;
    const int w    = tid >> 5;
    const int bid  = blockIdx.x;
    const int l0   = bid * LC;
    const int nloc = min(LC, L_ - l0);     // 56 or 40 (even)
    const int n32  = nloc * 32;
    const int H    = nloc >> 1;

    if (tid < 8)  s_nm[tid] = 0;
    if (tid < 32) { s_S1[tid] = 0; s_S2[tid] = 0; s_N[tid] = 0; }
    __syncthreads();

    // ---- staging: coalesced global loads (lanes walk consecutive loci) ----
    float ce_acc = 0.0f;
    for (int e = tid; e < n32; e += 1024) {
        int i  = e / nloc;                // batch
        int ll = e - i * nloc;            // local locus
        size_t gi = (size_t)i * L_ + l0 + ll;

        const float* yt = ytrue + gi * CF_;
        float lf = yt[1] + 2.0f * yt[2] + 3.0f * yt[3] + 4.0f * yt[4];
        int lbl = (int)(lf + 0.5f);

        float4 lg = logits4[gi];
        float m  = fmaxf(fmaxf(lg.x, lg.y), fmaxf(lg.z, lg.w));
        float se = __expf(lg.x - m) + __expf(lg.y - m) +
                   __expf(lg.z - m) + __expf(lg.w - m);
        if (lbl != 4) {
            float sel = (lbl == 0) ? lg.x : (lbl == 1) ? lg.y : (lbl == 2) ? lg.z : lg.w;
            ce_acc += (m + LN2F * __log2f(se)) - sel;
        }

        float4 p = prob4[gi];
        float a = fmaxf(p.x, 1e-7f), b = fmaxf(p.y, 1e-7f);
        float c = fmaxf(p.z, 1e-7f), d = fmaxf(p.w, 1e-7f);
        float hp = a * __log2f(a) + b * __log2f(b) +
                   c * __log2f(c) + d * __log2f(d) + (a + b + c + d);
        unsigned hb = (__float_as_uint(hp) + 0x8000u) & 0xFFFF0000u;

        __half2 p01 = __floats2half2_rn(a, b);
        __half2 p23 = __floats2half2_rn(c, d);
        int idx = ll * SROW + i;
        s_p[idx] = make_uint2(reinterpret_cast<unsigned&>(p01),
                              reinterpret_cast<unsigned&>(p23));
        s_m[idx] = hb | (unsigned)lbl;
    }

    // CE: warp partials -> CTA sum -> one deterministic fixed-point atomic
#pragma unroll
    for (int o = 16; o > 0; o >>= 1) ce_acc += __shfl_xor_sync(0xFFFFFFFFu, ce_acc, o);
    if (lane == 0) s_red[w] = ce_acc;
    __syncthreads();
    if (tid == 0) {
        float s = 0.0f;
#pragma unroll
        for (int k = 0; k < 32; ++k) s += s_red[k];
        atomicAdd((unsigned long long*)&g_ce_acc,
                  (unsigned long long)(long long)(s * SCALE_S));
    }

    // ---- r2 sufficient statistics per (group, alt) bucket ----
    if (tid < nloc * 8) {
        int g  = tid & 7;
        int ll = tid >> 3;
        int base = ll * SROW + g * 4;
        float pred = 0.0f;
        int alt = 0, nm = 0;
#pragma unroll
        for (int q = 0; q < 4; ++q) {
            uint2 u = s_p[base + q];
            float2 f01 = __half22float2(reinterpret_cast<__half2&>(u.x));
            float2 f23 = __half22float2(reinterpret_cast<__half2&>(u.y));
            pred += f01.y + f23.x + f23.y;
            int lb = s_m[base + q] & 0xFF;
            alt += (lb >= 1 && lb <= 3);
            nm  |= (lb != 4);
        }
        pred *= 0.25f;
        if (nm) {
            atomicAdd(&s_nm[g], 1);
            if (alt >= 1) {                       // alt==0 => af2==0 edge => 0
                int bkt = g * 4 + (alt - 1);
                atomicAdd(&s_S1[bkt], (int)(pred * SCALE_S + 0.5f));
                atomicAdd(&s_S2[bkt], (int)(pred * pred * SCALE_S + 0.5f));
                atomicAdd(&s_N[bkt], 1);
            }
        }
    }
    __syncthreads();
    if (tid < 32 && s_N[tid] > 0) {
        atomicAdd((unsigned long long*)&g_S1[tid], (unsigned long long)(long long)s_S1[tid]);
        atomicAdd((unsigned long long*)&g_S2[tid], (unsigned long long)(long long)s_S2[tid]);
        atomicAdd(&g_N[tid], s_N[tid]);
    }
    if (tid < 8 && s_nm[tid] > 0) atomicAdd(&g_nm_tot[tid], s_nm[tid]);

    // ---- symmetric pairwise JS (proven uniform loop) ----
    const int i = w;
    const int j = lane;
    const int start = (j < i) ? H : 0;

    float js = 0.0f;
    int   cnt = 0;
#pragma unroll 2
    for (int k = 0; k < H; ++k) {
        const int row = (start + k) * SROW;
        unsigned wi = s_m[row + i];           // broadcast
        if ((wi & 0xFFu) == 4u) continue;     // warp-uniform skip (20% of loci)
        unsigned wj = s_m[row + j];
        bool act = (((wi ^ wj) & 0xFFu) == 0u);
        float msk = act ? 1.0f : 0.0f;
        uint2 ui = s_p[row + i];              // broadcast
        uint2 uj = s_p[row + j];
        __half2 s01 = __hadd2(reinterpret_cast<__half2&>(ui.x),
                              reinterpret_cast<__half2&>(uj.x));
        __half2 s23 = __hadd2(reinterpret_cast<__half2&>(ui.y),
                              reinterpret_cast<__half2&>(uj.y));
        float2 f01 = __half22float2(s01);
        float2 f23 = __half22float2(s23);
        float slog2 = f01.x * __log2f(f01.x) + f01.y * __log2f(f01.y) +
                      f23.x * __log2f(f23.x) + f23.y * __log2f(f23.y);
        float hsum = __uint_as_float(wi & 0xFFFF0000u) +
                     __uint_as_float(wj & 0xFFFF0000u);
        js  = fmaf(msk, hsum - slog2, js);    // HLN2F applied at finalize
        cnt += act;
    }

    // direct fixed-point accumulation (order-independent => deterministic)
    atomicAdd((unsigned long long*)&g_js_acc[tid],
              (unsigned long long)(long long)(js * SCALE_JS));
    if (cnt) atomicAdd(&g_cnt_acc[tid], cnt);

    // ---- arrival: last-arriving CTA finalizes; nobody waits ----
    __threadfence();
    __syncthreads();
    if (tid == 0) s_last = (atomicAdd(&g_done, 1u) == NB - 1);
    __syncthreads();
    if (!s_last) return;
    __threadfence();

    // ================= finalize (one CTA, ~16KB of reads) =================
    // r2 in closed form over 32 buckets (warp 0)
    float r2w = 0.0f;
    if (tid < 32) {
        int g   = tid >> 2;
        int alt = (tid & 3) + 1;
        int Nb  = g_N[tid];
        if (Nb > 0) {
            float cntg = fmaxf(4.0f * (float)g_nm_tot[g], 1.0f);
            float af2  = (float)alt / cntg;
            if (af2 != 1.0f) {                    // af2>0 since alt>=1
                double S1 = (double)g_S1[tid] * ISCALE_S;
                double S2 = (double)g_S2[tid] * ISCALE_S;
                double a  = (double)af2;
                double den = fmax(a * (1.0 - a), 0.01);
                r2w = (float)((S2 - 2.0 * a * S1 + (double)Nb * a * a) / den);
            }
        }
#pragma unroll
        for (int o = 16; o > 0; o >>= 1) r2w += __shfl_xor_sync(0xFFFFFFFFu, r2w, o);
    }
    if (tid == 0) s_red[0] = r2w;                 // stash r2 total

    // evo combine: transpose symmetric halves, weights
    s_j[tid] = (float)((double)g_js_acc[tid] * ISCALE_JS);
    s_c[tid] = g_cnt_acc[tid];
    __syncthreads();
    float r2tot = s_red[0];
    const int tT = lane * 32 + w;
    float jsv = HLN2F * (s_j[tid] + s_j[tT]) /
                fmaxf((float)(s_c[tid] + s_c[tT]), 1.0f);
    float wgt = __expf(-yevo[tid]);
    float rs = wgt;
#pragma unroll
    for (int o = 16; o > 0; o >>= 1) rs += __shfl_xor_sync(0xFFFFFFFFu, rs, o);
    float term = (wgt / (rs + 1e-8f)) * jsv;
#pragma unroll
    for (int o = 16; o > 0; o >>= 1) term += __shfl_xor_sync(0xFFFFFFFFu, term, o);
    __syncthreads();
    if (lane == 0) s_red[w] = term;
    __syncthreads();
    if (tid == 0) {
        float evo = 0.0f;
#pragma unroll
        for (int k = 0; k < 32; ++k) evo += s_red[k];
        float ce = (float)((double)g_ce_acc * ISCALE_S);
        if (!isfinite(evo)) evo = 0.0f;
        out[0] = ce - 0.125f * r2tot + evo;   // r2_loss = -sum*GS/B
    }

    // reset accumulators for the next graph replay
    __syncthreads();
    g_js_acc[tid] = 0ll;
    g_cnt_acc[tid] = 0;
    if (tid < 32) { g_S1[tid] = 0ll; g_S2[tid] = 0ll; g_N[tid] = 0; }
    if (tid < 8)  g_nm_tot[tid] = 0;
    if (tid == 0) { g_ce_acc = 0ll; g_done = 0u; }
}

extern "C" void kernel_launch(void* const* d_in, const int* in_sizes, int n_in,
                              void* d_out, int out_size)
{
    const float* logits = (const float*)d_in[0];
    const float* prob   = (const float*)d_in[1];
    const float* ytrue  = (const float*)d_in[2];
    const float* yevo   = (const float*)d_in[3];

    k_fused<<<NB, 1024>>>((const float4*)logits, (const float4*)prob,
                          ytrue, yevo, (float*)d_out);
}